// round 3
// baseline (speedup 1.0000x reference)
#include <cuda_runtime.h>
#include <math.h>

#define Tt 1024
#define Bx 64
#define Ii 256
#define Hh 512
#define NM 65536          // B*T columns of the transposed projection
#define NBLK 128          // persistent blocks (all co-resident: 128 < 148 SMs)
#define TPB 512
#define CLIPV 5.0f

// ---- static device scratch (no allocation allowed) ----
__device__ float g_xall[1536u * 65536u];   // [gate][t*64+b]  (384 MB)
__device__ float g_hT[Hh * Bx];            // h transposed [j][b]
__device__ float g_rhT[Hh * Bx];           // (r*h) transposed [j][b]
__device__ unsigned g_bar;

// --------------------------------------------------------------------------
__global__ void init_kernel(const float* __restrict__ h0) {
    int b = blockIdx.x, j = threadIdx.x;
    g_hT[j * Bx + b] = h0[b * Hh + j];
    if (b == 0 && j == 0) g_bar = 0u;
}

// --------------------------------------------------------------------------
// xall[g][m] = sum_i W_ih[g][i] * x[b,t,i] + b_ih[g],  m = t*64 + b
// 128x128x32 tiles, 256 threads, 8x8 register tile.
__global__ __launch_bounds__(256) void xgemm_kernel(const float* __restrict__ x,
                                                    const float* __restrict__ Wih,
                                                    const float* __restrict__ bih) {
    __shared__ float As[32 * 132];
    __shared__ float Bs[32 * 132];
    const int tid = threadIdx.x;
    const int c  = tid & 31;     // k within tile
    const int r0 = tid >> 5;     // 0..7
    const int n0 = blockIdx.x * 128;
    const int g0 = blockIdx.y * 128;
    const int ty = tid >> 4, tx = tid & 15;

    float acc[8][8];
#pragma unroll
    for (int i = 0; i < 8; i++)
#pragma unroll
        for (int j = 0; j < 8; j++) acc[i][j] = 0.0f;

    for (int kt = 0; kt < 8; ++kt) {
        const int k0 = kt * 32;
#pragma unroll
        for (int rr = 0; rr < 16; ++rr) {
            const int r = rr * 8 + r0;
            As[c * 132 + r] = Wih[(g0 + r) * Ii + k0 + c];
            const int m = n0 + r;
            Bs[c * 132 + r] = x[((size_t)(m & 63) * Tt + (m >> 6)) * Ii + k0 + c];
        }
        __syncthreads();
#pragma unroll
        for (int k = 0; k < 32; ++k) {
            float a[8], bb[8];
            *(float4*)&a[0]  = *(const float4*)&As[k * 132 + ty * 8];
            *(float4*)&a[4]  = *(const float4*)&As[k * 132 + ty * 8 + 4];
            *(float4*)&bb[0] = *(const float4*)&Bs[k * 132 + tx * 8];
            *(float4*)&bb[4] = *(const float4*)&Bs[k * 132 + tx * 8 + 4];
#pragma unroll
            for (int i = 0; i < 8; i++)
#pragma unroll
                for (int j = 0; j < 8; j++) acc[i][j] += a[i] * bb[j];
        }
        __syncthreads();
    }
#pragma unroll
    for (int i = 0; i < 8; i++) {
        const int g = g0 + ty * 8 + i;
        const float bias = __ldg(&bih[g]);
        float* dst = &g_xall[(size_t)g * NM + n0 + tx * 8];
        *(float4*)&dst[0] = make_float4(acc[i][0] + bias, acc[i][1] + bias,
                                        acc[i][2] + bias, acc[i][3] + bias);
        *(float4*)&dst[4] = make_float4(acc[i][4] + bias, acc[i][5] + bias,
                                        acc[i][6] + bias, acc[i][7] + bias);
    }
}

// --------------------------------------------------------------------------
__device__ __forceinline__ void gridbar(unsigned target) {
    __threadfence();
    __syncthreads();
    if (threadIdx.x == 0) {
        atomicAdd(&g_bar, 1u);
        unsigned v;
        do {
            asm volatile("ld.acquire.gpu.u32 %0, [%1];" : "=r"(v) : "l"(&g_bar) : "memory");
            if (v >= target) break;
            __nanosleep(64);
        } while (true);
    }
    __syncthreads();
}

__device__ __forceinline__ void stage128k(float* hs, const float* src, int tid) {
    const float4* s4 = (const float4*)src;
#pragma unroll
    for (int it = 0; it < 16; ++it) {
        const int f4 = tid + (it << 9);          // 8192 float4 / 512 threads
        float4 v = __ldcg(&s4[f4]);              // L2-coherent read
        const int j = f4 >> 4, bq = f4 & 15;
        *(float4*)&hs[j * 68 + bq * 4] = v;
    }
}

// smem layout (floats): WA[8*516] | WB[4*516] | hs[512*68] | red[16*264] | bsh[16]
#define SM_WA 0
#define SM_WB 4128
#define SM_HS 6192
#define SM_RED 41008
#define SM_BSH 45232
#define SM_FLOATS 45248

__global__ __launch_bounds__(TPB) void gru_kernel(const float* __restrict__ Whh,
                                                  const float* __restrict__ bhhg,
                                                  float* __restrict__ out,
                                                  int out_size) {
    extern __shared__ float sm[];
    float* WA  = sm + SM_WA;     // z rows 0..3, r rows 4..7 (stride 516)
    float* WB  = sm + SM_WB;     // n rows 0..3
    float* hs  = sm + SM_HS;     // staged h / rh, [j][b] stride 68
    float* red = sm + SM_RED;
    float* bsh = sm + SM_BSH;

    const int tid = threadIdx.x;
    const int kbase = blockIdx.x * 4;

    // weight-stationary preload
    for (int i = tid; i < 12 * Hh; i += TPB) {
        const int row = i >> 9, j = i & 511;
        const int gr = (row < 4) ? (kbase + row)
                     : (row < 8) ? (512 + kbase + row - 4)
                                 : (1024 + kbase + row - 8);
        const float v = Whh[gr * Hh + j];
        if (row < 8) WA[row * 516 + j] = v;
        else         WB[(row - 8) * 516 + j] = v;
    }
    if (tid < 12) {
        const int row = tid;
        const int gr = (row < 4) ? (kbase + row)
                     : (row < 8) ? (512 + kbase + row - 4)
                                 : (1024 + kbase + row - 8);
        bsh[row] = bhhg[gr];
    }
    __syncthreads();

    // thread roles
    const int rowF = (tid >> 6) & 3;  const int bF = tid & 63;     // elementwise (tid<256)
    const int gA = tid & 7, rA = (tid >> 3) & 7, sA = tid >> 6;    // A: 8x8 rows x 8 jslices
    const int gB = tid & 7, rB = (tid >> 3) & 3, sB = tid >> 5;    // B: 4x8 rows x 16 jslices

    const float* xzp = g_xall + (size_t)(kbase + rowF) * NM + bF;
    const float* xrp = g_xall + (size_t)(512 + kbase + rowF) * NM + bF;
    const float* xnp = g_xall + (size_t)(1024 + kbase + rowF) * NM + bF;

    const bool wlast = (out_size >= Bx * Tt * Hh + Bx * Hh);
    unsigned target = NBLK;

    float z = 0.f, hold = 0.f, xn = 0.f;

    for (int t = 0; t < Tt; ++t) {
        float xz = 0.f, xr = 0.f;
        if (tid < 256) {
            const int xo = t * 64;
            xz = __ldg(xzp + xo); xr = __ldg(xrp + xo); xn = __ldg(xnp + xo);
        }

        // ---- stage h ----
        stage128k(hs, g_hT, tid);
        __syncthreads();

        // ---- phase A: hz/hr partial GEMM (1 row x 8 b, j-slice of 64) ----
        float acc[8];
#pragma unroll
        for (int i = 0; i < 8; i++) acc[i] = 0.f;
        {
            const float* wp = WA + rA * 516 + sA * 64;
            const float* hp = hs + sA * 64 * 68 + gA * 8;
#pragma unroll 4
            for (int jj = 0; jj < 64; ++jj) {
                const float w = wp[jj];
                const float4 h0 = *(const float4*)hp;
                const float4 h1 = *(const float4*)(hp + 4);
                acc[0] += w * h0.x; acc[1] += w * h0.y;
                acc[2] += w * h0.z; acc[3] += w * h0.w;
                acc[4] += w * h1.x; acc[5] += w * h1.y;
                acc[6] += w * h1.z; acc[7] += w * h1.w;
                hp += 68;
            }
        }
        {
            float* rp = red + sA * 520 + rA * 64 + gA * 8;
            *(float4*)rp       = make_float4(acc[0], acc[1], acc[2], acc[3]);
            *(float4*)(rp + 4) = make_float4(acc[4], acc[5], acc[6], acc[7]);
        }
        __syncthreads();

        if (tid < 256) {
            float hz = 0.f, hr = 0.f;
#pragma unroll
            for (int s = 0; s < 8; s++) {
                hz += red[s * 520 + tid];
                hr += red[s * 520 + 256 + tid];
            }
            z = 1.f / (1.f + __expf(-(xz + hz + bsh[rowF])));
            const float r = 1.f / (1.f + __expf(-(xr + hr + bsh[4 + rowF])));
            hold = hs[(kbase + rowF) * 68 + bF];
            __stcg(&g_rhT[(kbase + rowF) * 64 + bF], r * hold);
        }
        gridbar(target); target += NBLK;

        // ---- stage r*h ----
        stage128k(hs, g_rhT, tid);
        __syncthreads();

        // ---- phase B: hn partial GEMM (1 row x 8 b, j-slice of 32) ----
        float accb[8];
#pragma unroll
        for (int i = 0; i < 8; i++) accb[i] = 0.f;
        {
            const float* wp = WB + rB * 516 + sB * 32;
            const float* hp = hs + sB * 32 * 68 + gB * 8;
#pragma unroll 4
            for (int jj = 0; jj < 32; ++jj) {
                const float w = wp[jj];
                const float4 h0 = *(const float4*)hp;
                const float4 h1 = *(const float4*)(hp + 4);
                accb[0] += w * h0.x; accb[1] += w * h0.y;
                accb[2] += w * h0.z; accb[3] += w * h0.w;
                accb[4] += w * h1.x; accb[5] += w * h1.y;
                accb[6] += w * h1.z; accb[7] += w * h1.w;
                hp += 68;
            }
        }
        {
            float* rp = red + sB * 264 + rB * 64 + gB * 8;
            *(float4*)rp       = make_float4(accb[0], accb[1], accb[2], accb[3]);
            *(float4*)(rp + 4) = make_float4(accb[4], accb[5], accb[6], accb[7]);
        }
        __syncthreads();

        if (tid < 256) {
            float hn = 0.f;
#pragma unroll
            for (int s = 0; s < 16; s++) hn += red[s * 264 + tid];
            hn += bsh[8 + rowF];
            const float n = tanhf(xn + hn);
            float hnew = z * hold + (1.f - z) * n;
            hnew = fminf(CLIPV, fmaxf(-CLIPV, hnew));
            __stcg(&g_hT[(kbase + rowF) * 64 + bF], hnew);
            out[(size_t)bF * (Tt * Hh) + (size_t)t * Hh + kbase + rowF] = hnew;
            if (wlast && t == Tt - 1)
                out[(size_t)Bx * Tt * Hh + (size_t)bF * Hh + kbase + rowF] = hnew;
        }
        gridbar(target); target += NBLK;
    }
}

// --------------------------------------------------------------------------
extern "C" void kernel_launch(void* const* d_in, const int* in_sizes, int n_in,
                              void* d_out, int out_size) {
    const float* x   = (const float*)d_in[0];
    const float* h0  = (const float*)d_in[1];
    const float* Wih = (const float*)d_in[2];
    const float* bih = (const float*)d_in[3];
    const float* Whh = (const float*)d_in[4];
    const float* bhh = (const float*)d_in[5];
    float* out = (float*)d_out;

    init_kernel<<<Bx, Hh>>>(h0);

    dim3 gg(512, 12);
    xgemm_kernel<<<gg, 256>>>(x, Wih, bih);

    const int smem_bytes = SM_FLOATS * (int)sizeof(float);   // 180,992 B
    cudaFuncSetAttribute(gru_kernel, cudaFuncAttributeMaxDynamicSharedMemorySize,
                         smem_bytes);
    gru_kernel<<<NBLK, TPB, smem_bytes>>>(Whh, bhh, out, out_size);
}

// round 5
// speedup vs baseline: 1.7271x; 1.7271x over previous
#include <cuda_runtime.h>
#include <math.h>
typedef unsigned long long ull;

#define Tt 1024
#define Bx 64
#define Ii 256
#define Hh 512
#define NM 65536
#define TPB 256
#define CLIPV 5.0f
#define NGRP 4
#define BPG 32
#define GB 16
#define ROWS 16

__device__ float g_xall[1536u * 65536u];
__device__ float g_h[NGRP * Hh * GB];
__device__ float g_rh[NGRP * Hh * GB];
__device__ unsigned g_bar4[NGRP * 32];

__global__ void init_kernel(const float* __restrict__ h0) {
    int bg = blockIdx.x, j = threadIdx.x;
    g_h[(bg >> 4) * (Hh * GB) + j * GB + (bg & 15)] = h0[bg * Hh + j];
    if (bg == 0 && j < NGRP) g_bar4[j * 32] = 0u;
}

__global__ __launch_bounds__(256) void xgemm_kernel(const float* __restrict__ x,
                                                    const float* __restrict__ Wih,
                                                    const float* __restrict__ bih) {
    __shared__ float As[32 * 132];
    __shared__ float Bs[32 * 132];
    const int tid = threadIdx.x, c = tid & 31, r0 = tid >> 5;
    const int n0 = blockIdx.x * 128, g0 = blockIdx.y * 128;
    const int ty = tid >> 4, tx = tid & 15;
    float acc[8][8];
#pragma unroll
    for (int i = 0; i < 8; i++)
#pragma unroll
        for (int j = 0; j < 8; j++) acc[i][j] = 0.f;
    for (int kt = 0; kt < 8; ++kt) {
        const int k0 = kt * 32;
#pragma unroll
        for (int rr = 0; rr < 16; ++rr) {
            const int r = rr * 8 + r0;
            As[c * 132 + r] = Wih[(g0 + r) * Ii + k0 + c];
            const int m = n0 + r;
            Bs[c * 132 + r] = x[((size_t)(m & 63) * Tt + (m >> 6)) * Ii + k0 + c];
        }
        __syncthreads();
#pragma unroll
        for (int k = 0; k < 32; ++k) {
            float a[8], bb[8];
            *(float4*)&a[0]  = *(const float4*)&As[k * 132 + ty * 8];
            *(float4*)&a[4]  = *(const float4*)&As[k * 132 + ty * 8 + 4];
            *(float4*)&bb[0] = *(const float4*)&Bs[k * 132 + tx * 8];
            *(float4*)&bb[4] = *(const float4*)&Bs[k * 132 + tx * 8 + 4];
#pragma unroll
            for (int i = 0; i < 8; i++)
#pragma unroll
                for (int j = 0; j < 8; j++) acc[i][j] += a[i] * bb[j];
        }
        __syncthreads();
    }
#pragma unroll
    for (int i = 0; i < 8; i++) {
        const int g = g0 + ty * 8 + i;
        const float bias = __ldg(&bih[g]);
        float* dst = &g_xall[(size_t)g * NM + n0 + tx * 8];
        *(float4*)&dst[0] = make_float4(acc[i][0] + bias, acc[i][1] + bias,
                                        acc[i][2] + bias, acc[i][3] + bias);
        *(float4*)&dst[4] = make_float4(acc[i][4] + bias, acc[i][5] + bias,
                                        acc[i][6] + bias, acc[i][7] + bias);
    }
}

__device__ __forceinline__ ull pk2(float v) {
    ull r; asm("mov.b64 %0, {%1, %1};" : "=l"(r) : "f"(v)); return r;
}
__device__ __forceinline__ void fma2(ull& d, ull a, ull b) {
    asm("fma.rn.f32x2 %0, %1, %2, %0;" : "+l"(d) : "l"(a), "l"(b));
}
__device__ __forceinline__ float2 upk(ull v) {
    float2 f; asm("mov.b64 {%0, %1}, %2;" : "=f"(f.x), "=f"(f.y) : "l"(v)); return f;
}
__device__ __forceinline__ void groupbar(unsigned* ctr, unsigned target) {
    __syncthreads();
    if (threadIdx.x == 0) {
        asm volatile("red.release.gpu.add.u32 [%0], %1;" :: "l"(ctr), "r"(1u) : "memory");
        unsigned v;
        do {
            asm volatile("ld.acquire.gpu.u32 %0, [%1];" : "=r"(v) : "l"(ctr) : "memory");
        } while (v < target);
    }
    __syncthreads();
}
__device__ __forceinline__ void stage(float* hs, const float* src, int tid) {
    const float4* s4 = (const float4*)src;
#pragma unroll
    for (int k = 0; k < 8; ++k) {
        const int idx = tid + (k << 8);
        float4 v = __ldcg(&s4[idx]);
        *(float4*)&hs[(idx >> 2) * 20 + (idx & 3) * 4] = v;
    }
}

#define SM_WZR 0
#define SM_WN  18432
#define SM_HS  28672
#define SM_RED 38912
#define SM_BSH 44032
#define SM_FLOATS 44080

__global__ __launch_bounds__(TPB) void gru_kernel(const float* __restrict__ Whh,
                                                  const float* __restrict__ bhhg,
                                                  float* __restrict__ out,
                                                  int out_size) {
    extern __shared__ float sm[];
    float* WZR = sm + SM_WZR;   // [j][32 rows], stride 36
    float* WN  = sm + SM_WN;    // [j][16 rows], stride 20
    float* hs  = sm + SM_HS;    // [j][16 b], stride 20
    float* red = sm + SM_RED;
    float* bsh = sm + SM_BSH;

    const int tid = threadIdx.x;
    const int grp = blockIdx.x >> 5, rblk = blockIdx.x & 31;
    const int kbase = rblk * ROWS, bbase = grp * GB, gofs = grp * (Hh * GB);
    unsigned* ctr = &g_bar4[grp * 32];

    for (int i = tid; i < 32 * Hh; i += TPB) {
        const int row = i >> 9, j = i & 511;
        const int gr = (row < 16) ? (kbase + row) : (512 + kbase + row - 16);
        WZR[j * 36 + row] = Whh[gr * Hh + j];
    }
    for (int i = tid; i < 16 * Hh; i += TPB)
        WN[(i & 511) * 20 + (i >> 9)] = Whh[(1024 + kbase + (i >> 9)) * Hh + (i & 511)];
    if (tid < 48) {
        const int row = tid & 15;
        bsh[tid] = bhhg[(tid < 16 ? 0 : tid < 32 ? 512 : 1024) + kbase + row];
    }
    __syncthreads();

    const int rgA = tid & 3, bgA = (tid >> 2) & 1, jsA = tid >> 3;
    const int rgB = tid & 1, bgB = (tid >> 1) & 1, jsB = tid >> 2;
    const int wrp = tid >> 5, lane = tid & 31;
    const int hrow = tid >> 4, bb = tid & 15;

    const size_t xo0 = (size_t)(kbase + hrow) * NM + (bbase + bb);
    const bool wlast = out_size > Bx * Tt * Hh;
    float h_own = g_h[gofs + (kbase + hrow) * GB + bb];
    unsigned tgt = BPG;

    for (int t = 0; t < Tt; ++t) {
        const size_t xo = xo0 + (size_t)t * 64;
        const float xz = __ldg(&g_xall[xo]);
        const float xr = __ldg(&g_xall[xo + (size_t)512 * NM]);
        const float xn = __ldg(&g_xall[xo + (size_t)1024 * NM]);

        stage(hs, g_h + gofs, tid);
        __syncthreads();

        ull acc[8][4];
#pragma unroll
        for (int r = 0; r < 8; r++)
#pragma unroll
            for (int p = 0; p < 4; p++) acc[r][p] = 0ull;
        {
            const float* hb = hs + bgA * 8;
            const float* wb = WZR + rgA * 8;
#pragma unroll
            for (int jj = 0; jj < 16; ++jj) {
                const int j = jsA + (jj << 5);
                ulonglong2 hA = *(const ulonglong2*)(hb + j * 20);
                ulonglong2 hB = *(const ulonglong2*)(hb + j * 20 + 4);
                const float4 wa = *(const float4*)(wb + j * 36);
                const float4 wc = *(const float4*)(wb + j * 36 + 4);
                ull wk[8] = {pk2(wa.x), pk2(wa.y), pk2(wa.z), pk2(wa.w),
                             pk2(wc.x), pk2(wc.y), pk2(wc.z), pk2(wc.w)};
#pragma unroll
                for (int r = 0; r < 8; r++) {
                    fma2(acc[r][0], wk[r], hA.x); fma2(acc[r][1], wk[r], hA.y);
                    fma2(acc[r][2], wk[r], hB.x); fma2(acc[r][3], wk[r], hB.y);
                }
            }
        }
        {
            float accf[64];
#pragma unroll
            for (int r = 0; r < 8; r++)
#pragma unroll
                for (int p = 0; p < 4; p++) {
                    float2 f = upk(acc[r][p]);
                    accf[r * 8 + p * 2] = f.x; accf[r * 8 + p * 2 + 1] = f.y;
                }
#pragma unroll
            for (int i = 0; i < 64; i++) {
                accf[i] += __shfl_xor_sync(~0u, accf[i], 8, 32);
                accf[i] += __shfl_xor_sync(~0u, accf[i], 16, 32);
            }
            const int q = (lane >> 3) & 3;
            float* rw = red + wrp * 640 + bgA * 8;
#pragma unroll
            for (int rr = 0; rr < 2; ++rr) {
                const int r = 2 * q + rr;
                float* p = rw + (rgA * 8 + r) * 20;
                *(float4*)p = make_float4(accf[r*8], accf[r*8+1], accf[r*8+2], accf[r*8+3]);
                *(float4*)(p + 4) = make_float4(accf[r*8+4], accf[r*8+5], accf[r*8+6], accf[r*8+7]);
            }
        }
        __syncthreads();

        float z;
        {
            float hz = 0.f, hr = 0.f;
#pragma unroll
            for (int w = 0; w < 8; w++) {
                hz += red[w * 640 + hrow * 20 + bb];
                hr += red[w * 640 + (16 + hrow) * 20 + bb];
            }
            z = 1.f / (1.f + __expf(-(xz + hz + bsh[hrow])));
            const float r = 1.f / (1.f + __expf(-(xr + hr + bsh[16 + hrow])));
            __stcg(&g_rh[gofs + (kbase + hrow) * GB + bb], r * h_own);
        }
        groupbar(ctr, tgt); tgt += BPG;

        stage(hs, g_rh + gofs, tid);
        __syncthreads();

        ull acb[8][4];
#pragma unroll
        for (int r = 0; r < 8; r++)
#pragma unroll
            for (int p = 0; p < 4; p++) acb[r][p] = 0ull;
        {
            const float* hb = hs + bgB * 8;
            const float* wb = WN + rgB * 8;
#pragma unroll
            for (int jj = 0; jj < 8; ++jj) {
                const int j = jsB + (jj << 6);
                ulonglong2 hA = *(const ulonglong2*)(hb + j * 20);
                ulonglong2 hB = *(const ulonglong2*)(hb + j * 20 + 4);
                const float4 wa = *(const float4*)(wb + j * 20);
                const float4 wc = *(const float4*)(wb + j * 20 + 4);
                ull wk[8] = {pk2(wa.x), pk2(wa.y), pk2(wa.z), pk2(wa.w),
                             pk2(wc.x), pk2(wc.y), pk2(wc.z), pk2(wc.w)};
#pragma unroll
                for (int r = 0; r < 8; r++) {
                    fma2(acb[r][0], wk[r], hA.x); fma2(acb[r][1], wk[r], hA.y);
                    fma2(acb[r][2], wk[r], hB.x); fma2(acb[r][3], wk[r], hB.y);
                }
            }
        }
        {
            float accf[64];
#pragma unroll
            for (int r = 0; r < 8; r++)
#pragma unroll
                for (int p = 0; p < 4; p++) {
                    float2 f = upk(acb[r][p]);
                    accf[r * 8 + p * 2] = f.x; accf[r * 8 + p * 2 + 1] = f.y;
                }
#pragma unroll
            for (int i = 0; i < 64; i++) {
                accf[i] += __shfl_xor_sync(~0u, accf[i], 4, 32);
                accf[i] += __shfl_xor_sync(~0u, accf[i], 8, 32);
                accf[i] += __shfl_xor_sync(~0u, accf[i], 16, 32);
            }
            const int r = (lane >> 2) & 7;
            float* p = red + wrp * 320 + (rgB * 8 + r) * 20 + bgB * 8;
            *(float4*)p = make_float4(accf[r*8], accf[r*8+1], accf[r*8+2], accf[r*8+3]);
            *(float4*)(p + 4) = make_float4(accf[r*8+4], accf[r*8+5], accf[r*8+6], accf[r*8+7]);
        }
        __syncthreads();

        {
            float hn = 0.f;
#pragma unroll
            for (int w = 0; w < 8; w++) hn += red[w * 320 + hrow * 20 + bb];
            const float n = tanhf(xn + hn + bsh[32 + hrow]);
            float hnew = z * h_own + (1.f - z) * n;
            hnew = fminf(CLIPV, fmaxf(-CLIPV, hnew));
            h_own = hnew;
            __stcg(&g_h[gofs + (kbase + hrow) * GB + bb], hnew);
            out[((size_t)(bbase + bb) * Tt + t) * Hh + kbase + hrow] = hnew;
            if (wlast && t == Tt - 1)
                out[(size_t)Bx * Tt * Hh + (size_t)(bbase + bb) * Hh + kbase + hrow] = hnew;
        }
        groupbar(ctr, tgt); tgt += BPG;
    }
}

extern "C" void kernel_launch(void* const* d_in, const int* in_sizes, int n_in,
                              void* d_out, int out_size) {
    const float* x   = (const float*)d_in[0];
    const float* h0  = (const float*)d_in[1];
    const float* Wih = (const float*)d_in[2];
    const float* bih = (const float*)d_in[3];
    const float* Whh = (const float*)d_in[4];
    const float* bhh = (const float*)d_in[5];
    float* out = (float*)d_out;

    init_kernel<<<Bx, Hh>>>(h0);
    dim3 gg(512, 12);
    xgemm_kernel<<<gg, 256>>>(x, Wih, bih);
    const int smem = SM_FLOATS * (int)sizeof(float);
    cudaFuncSetAttribute(gru_kernel, cudaFuncAttributeMaxDynamicSharedMemorySize, smem);
    gru_kernel<<<NGRP * BPG, TPB, smem>>>(Whh, bhh, out, out_size);
}